// round 1
// baseline (speedup 1.0000x reference)
#include <cuda_runtime.h>
#include <cuda_bf16.h>

// Problem dims
#define TT 8192
#define DIN 2048
#define DD 512
#define HH 512
#define AA 18
#define H3 1536

// GRU persistent-kernel config
#define NC 64          // CTAs
#define CHUNK 8        // h indices per CTA (512/64)
#define GT 16          // threads per h-index (k split)
#define KPT 32         // k values per thread (512/16)
#define GRU_THREADS (CHUNK*GT)  // 128

// ---------------- scratch (device globals; no allocation allowed) ----------------
__device__ float g_z1[(size_t)TT * DD];
__device__ float g_z2[(size_t)TT * DD];
__device__ float g_X[(size_t)TT * H3];
__device__ float g_seq[(size_t)TT * HH];
__device__ float g_h[2 * HH];
__device__ int   g_flags[NC];

// ---------------- init ----------------
__global__ void k_init(const float* __restrict__ prev_hidden) {
    int i = threadIdx.x;
    if (i < NC) g_flags[i] = 0;
    if (i < HH) g_h[i] = prev_hidden[i];
}

// ---------------- SGEMM (fp32, register blocked) ----------------
// C[M,N] = act(A[M,K] @ B[K,N] + bias[N]); BM=128 BN=64 BK=16, 256 threads, 8x4/thread
__device__ __forceinline__ void sgemm_body(
    const float* __restrict__ A, const float* __restrict__ B,
    const float* __restrict__ bias, float* __restrict__ C,
    int M, int N, int K, bool relu)
{
    constexpr int BM = 128, BN = 64, BK = 16, TM = 8, TN = 4;
    __shared__ float As[BK][BM];
    __shared__ float Bs[BK][BN];

    const int tid = threadIdx.x;         // 256 threads
    const int tx = tid & 15;             // 16 col groups
    const int ty = tid >> 4;             // 16 row groups
    const int row0 = ty * TM;
    const int col0 = tx * TN;
    const int rowBase = blockIdx.y * BM;
    const int colBase = blockIdx.x * BN;

    float acc[TM][TN];
#pragma unroll
    for (int i = 0; i < TM; i++)
#pragma unroll
        for (int j = 0; j < TN; j++) acc[i][j] = 0.f;

    for (int k0 = 0; k0 < K; k0 += BK) {
        // Load A tile (128x16) -> transposed into As[BK][BM]
#pragma unroll
        for (int i = 0; i < 2; i++) {
            int idx = tid * 2 + i;             // 0..511
            int r = idx >> 2;                  // 0..127
            int c4 = (idx & 3) * 4;            // 0,4,8,12
            float4 v = *(const float4*)(A + (size_t)(rowBase + r) * K + k0 + c4);
            As[c4 + 0][r] = v.x;
            As[c4 + 1][r] = v.y;
            As[c4 + 2][r] = v.z;
            As[c4 + 3][r] = v.w;
        }
        // Load B tile (16x64)
        {
            int r = tid >> 4;                  // 0..15
            int c = (tid & 15) * 4;            // 0..60
            *(float4*)&Bs[r][c] = *(const float4*)(B + (size_t)(k0 + r) * N + colBase + c);
        }
        __syncthreads();

#pragma unroll
        for (int kk = 0; kk < BK; kk++) {
            float4 a0 = *(float4*)&As[kk][row0];
            float4 a1 = *(float4*)&As[kk][row0 + 4];
            float4 b0 = *(float4*)&Bs[kk][col0];
            float a[TM] = {a0.x, a0.y, a0.z, a0.w, a1.x, a1.y, a1.z, a1.w};
            float b[TN] = {b0.x, b0.y, b0.z, b0.w};
#pragma unroll
            for (int i = 0; i < TM; i++)
#pragma unroll
                for (int j = 0; j < TN; j++)
                    acc[i][j] = fmaf(a[i], b[j], acc[i][j]);
        }
        __syncthreads();
    }

    // Epilogue
    float4 bv = *(const float4*)(bias + colBase + col0);
    float bb[TN] = {bv.x, bv.y, bv.z, bv.w};
#pragma unroll
    for (int i = 0; i < TM; i++) {
        float4 o;
        float v0 = acc[i][0] + bb[0];
        float v1 = acc[i][1] + bb[1];
        float v2 = acc[i][2] + bb[2];
        float v3 = acc[i][3] + bb[3];
        if (relu) {
            v0 = fmaxf(v0, 0.f); v1 = fmaxf(v1, 0.f);
            v2 = fmaxf(v2, 0.f); v3 = fmaxf(v3, 0.f);
        }
        o.x = v0; o.y = v1; o.z = v2; o.w = v3;
        *(float4*)(C + (size_t)(rowBase + row0 + i) * N + colBase + col0) = o;
    }
}

__global__ __launch_bounds__(256) void k_gemm1(const float* __restrict__ x,
                                               const float* __restrict__ W1,
                                               const float* __restrict__ b1) {
    sgemm_body(x, W1, b1, g_z1, TT, DD, DIN, true);
}
__global__ __launch_bounds__(256) void k_gemm2(const float* __restrict__ W2,
                                               const float* __restrict__ b2) {
    sgemm_body(g_z1, W2, b2, g_z2, TT, DD, DD, true);
}
__global__ __launch_bounds__(256) void k_gemm3(const float* __restrict__ Wg,
                                               const float* __restrict__ bg) {
    // bias = bg row 0 (input bias)
    sgemm_body(g_z2, Wg, bg, g_X, TT, H3, DD, false);
}

// ---------------- GRU sequential scan (persistent, flag-synced) ----------------
__device__ __forceinline__ float sigmoidf_(float x) {
    return 1.0f / (1.0f + __expf(-x));
}

__global__ __launch_bounds__(GRU_THREADS, 1) void k_gru(
    const float* __restrict__ Ug,   // [512, 1536]
    const float* __restrict__ bg)   // [2, 1536]; row 1 = recurrent bias
{
    const int tid = threadIdx.x;       // 0..127
    const int g = tid >> 4;            // 0..7   (h index within chunk)
    const int s = tid & 15;            // 0..15  (k split)
    const int cta = blockIdx.x;        // 0..63
    const int base = cta * CHUNK;
    const int col = base + g;          // h index 0..511
    const bool leader = (s == 0);

    __shared__ float sh_h[CHUNK];

    // Register-resident recurrent weights: 3 gates x KPT k-values
    float w[3][KPT];
#pragma unroll
    for (int q = 0; q < 3; q++) {
        const float* ugc = Ug + (size_t)q * HH + col;
#pragma unroll
        for (int m = 0; m < KPT; m++)
            w[q][m] = ugc[(size_t)(s * KPT + m) * H3];
    }
    float br[3] = {0.f, 0.f, 0.f};
    if (leader) {
#pragma unroll
        for (int q = 0; q < 3; q++) br[q] = bg[H3 + q * HH + col];
    }

    volatile int* vf = g_flags;

    for (int t = 0; t < TT; t++) {
        // Prefetch input projections for this step (independent of h)
        float xg0 = 0.f, xg1 = 0.f, xg2 = 0.f;
        if (leader) {
            const float* xr = g_X + (size_t)t * H3 + col;
            xg0 = xr[0];
            xg1 = xr[HH];
            xg2 = xr[2 * HH];
        }

        // Wait until every CTA has published h_t
        if (tid < 32) {
            for (;;) {
                int f1 = vf[tid];
                int f2 = vf[tid + 32];
                if (__all_sync(0xffffffffu, (f1 >= t) && (f2 >= t))) break;
            }
        }
        __syncthreads();

        const float* hb = g_h + (t & 1) * HH;

        // Leader also needs h_old[col]
        float hold = 0.f;
        if (leader) hold = __ldcg(hb + col);

        // Load my k slice of h (bypass L1: buffer is rewritten every 2 steps)
        float hr[KPT];
#pragma unroll
        for (int i = 0; i < KPT / 4; i++) {
            float4 v = __ldcg((const float4*)(hb + s * KPT + i * 4));
            hr[i * 4 + 0] = v.x; hr[i * 4 + 1] = v.y;
            hr[i * 4 + 2] = v.z; hr[i * 4 + 3] = v.w;
        }

        // Partial matvec: 3 gate columns
        float a0 = 0.f, a1 = 0.f, a2 = 0.f;
#pragma unroll
        for (int m = 0; m < KPT; m++) {
            a0 = fmaf(hr[m], w[0][m], a0);
            a1 = fmaf(hr[m], w[1][m], a1);
            a2 = fmaf(hr[m], w[2][m], a2);
        }
        // Reduce over the 16-thread group (xor butterfly stays in 16-lane half)
#pragma unroll
        for (int off = 8; off >= 1; off >>= 1) {
            a0 += __shfl_xor_sync(0xffffffffu, a0, off);
            a1 += __shfl_xor_sync(0xffffffffu, a1, off);
            a2 += __shfl_xor_sync(0xffffffffu, a2, off);
        }

        if (leader) {
            float rz = a0 + br[0];
            float rr = a1 + br[1];
            float rh = a2 + br[2];
            float zt = sigmoidf_(xg0 + rz);
            float rt = sigmoidf_(xg1 + rr);
            float hh = sigmoidf_(xg2 + rt * rh);
            float hn = zt * hold + (1.f - zt) * hh;
            sh_h[g] = hn;
            __stcs(g_seq + (size_t)t * HH + col, hn);
        }
        __syncthreads();

        if (tid == 0) {
            float* hbn = g_h + ((t + 1) & 1) * HH + base;
            float4 v0 = *(float4*)&sh_h[0];
            float4 v1 = *(float4*)&sh_h[4];
            __stcg((float4*)hbn, v0);
            __stcg((float4*)(hbn + 4), v1);
            __threadfence();
            vf[cta] = t + 1;
        }
        // No trailing barrier needed: next iteration's post-poll __syncthreads
        // gates everyone, and sh_h is only rewritten after that barrier.
    }
}

// ---------------- Heads: policy softmax + value + hT ----------------
__global__ __launch_bounds__(256) void k_head(
    const float* __restrict__ Wp, const float* __restrict__ bp,
    const float* __restrict__ Wv, const float* __restrict__ bv,
    float* __restrict__ policy, float* __restrict__ value, float* __restrict__ hT)
{
    __shared__ float sWp[HH * AA];   // 36 KB
    __shared__ float sWv[HH];
    __shared__ float sbp[AA];

    const int tid = threadIdx.x;
    for (int i = tid; i < HH * AA; i += 256) sWp[i] = Wp[i];
    for (int i = tid; i < HH; i += 256) sWv[i] = Wv[i];
    if (tid < AA) sbp[tid] = bp[tid];
    __syncthreads();

    // hT = seq[T-1]
    if (blockIdx.x == 0) {
        for (int i = tid; i < HH; i += 256) hT[i] = g_seq[(size_t)(TT - 1) * HH + i];
    }

    const int warp = tid >> 5;
    const int lane = tid & 31;
    const int gwarp = blockIdx.x * 8 + warp;
    const int nwarps = gridDim.x * 8;
    const float bvv = bv[0];

    for (int row = gwarp; row < TT; row += nwarps) {
        float acc[AA + 1];
#pragma unroll
        for (int o = 0; o <= AA; o++) acc[o] = 0.f;

        const float* hrow = g_seq + (size_t)row * HH;
#pragma unroll 4
        for (int i = 0; i < HH / 32; i++) {
            int k = i * 32 + lane;
            float h = hrow[k];
            const float* wr = &sWp[k * AA];
#pragma unroll
            for (int o = 0; o < AA; o++) acc[o] = fmaf(h, wr[o], acc[o]);
            acc[AA] = fmaf(h, sWv[k], acc[AA]);
        }
#pragma unroll
        for (int off = 16; off >= 1; off >>= 1) {
#pragma unroll
            for (int o = 0; o <= AA; o++)
                acc[o] += __shfl_xor_sync(0xffffffffu, acc[o], off);
        }
        if (lane == 0) {
            float logits[AA];
            float mx = -1e30f;
#pragma unroll
            for (int o = 0; o < AA; o++) {
                logits[o] = acc[o] + sbp[o];
                mx = fmaxf(mx, logits[o]);
            }
            float sum = 0.f;
#pragma unroll
            for (int o = 0; o < AA; o++) {
                logits[o] = __expf(logits[o] - mx);
                sum += logits[o];
            }
            float inv = 1.f / sum;
            float* prow = policy + (size_t)row * AA;
#pragma unroll
            for (int o = 0; o < AA; o++) prow[o] = logits[o] * inv;
            value[row] = acc[AA] + bvv;
        }
    }
}

// ---------------- launch ----------------
extern "C" void kernel_launch(void* const* d_in, const int* in_sizes, int n_in,
                              void* d_out, int out_size) {
    const float* x    = (const float*)d_in[0];
    const float* prev = (const float*)d_in[1];
    const float* W1   = (const float*)d_in[2];
    const float* b1   = (const float*)d_in[3];
    const float* W2   = (const float*)d_in[4];
    const float* b2   = (const float*)d_in[5];
    const float* Wg   = (const float*)d_in[6];
    const float* Ug   = (const float*)d_in[7];
    const float* bg   = (const float*)d_in[8];
    const float* Wp   = (const float*)d_in[9];
    const float* bp   = (const float*)d_in[10];
    const float* Wv   = (const float*)d_in[11];
    const float* bv   = (const float*)d_in[12];

    float* out    = (float*)d_out;
    float* policy = out;                       // [T, A]
    float* value  = out + (size_t)TT * AA;     // [T, 1]
    float* hT     = out + (size_t)TT * AA + TT;// [1, H]

    k_init<<<1, 512>>>(prev);

    dim3 blk(256);
    k_gemm1<<<dim3(DD / 64, TT / 128), blk>>>(x, W1, b1);
    k_gemm2<<<dim3(DD / 64, TT / 128), blk>>>(W2, b2);
    k_gemm3<<<dim3(H3 / 64, TT / 128), blk>>>(Wg, bg);

    k_gru<<<NC, GRU_THREADS>>>(Ug, bg);

    k_head<<<256, 256>>>(Wp, bp, Wv, bv, policy, value, hT);

    (void)in_sizes; (void)n_in; (void)out_size;
}

// round 2
// speedup vs baseline: 1.0123x; 1.0123x over previous
#include <cuda_runtime.h>
#include <cuda_bf16.h>

// Problem dims
#define TT 8192
#define DIN 2048
#define DD 512
#define HH 512
#define AA 18
#define H3 1536

// GRU persistent-kernel config
#define NCG 64         // CTAs
#define GRU_THREADS 128

typedef unsigned long long ull;

// ---------------- scratch (device globals; no allocation allowed) ----------------
__device__ float g_z1[(size_t)TT * DD];
__device__ float g_z2[(size_t)TT * DD];
__device__ float g_X[(size_t)TT * H3];
__device__ float g_seq[(size_t)TT * HH];
__device__ float g_h[2 * HH];
__device__ int   g_cnt;

// ---------------- packed f32x2 helpers (sm_103a FFMA2) ----------------
__device__ __forceinline__ ull pk2(float lo, float hi) {
    ull r; asm("mov.b64 %0,{%1,%2};" : "=l"(r) : "f"(lo), "f"(hi)); return r;
}
__device__ __forceinline__ float2 upk2(ull v) {
    float2 r; asm("mov.b64 {%0,%1},%2;" : "=f"(r.x), "=f"(r.y) : "l"(v)); return r;
}
#define FMA2(d, a, b) asm("fma.rn.f32x2 %0,%1,%2,%0;" : "+l"(d) : "l"(a), "l"(b))

// ---------------- gpu-scope acquire/release primitives ----------------
__device__ __forceinline__ int ld_acq(const int* p) {
    int v; asm volatile("ld.acquire.gpu.global.s32 %0,[%1];" : "=r"(v) : "l"(p)); return v;
}
__device__ __forceinline__ void red_rel_add(int* p, int v) {
    asm volatile("red.release.gpu.global.add.s32 [%0],%1;" :: "l"(p), "r"(v) : "memory");
}

// ---------------- init ----------------
__global__ void k_init(const float* __restrict__ prev_hidden) {
    int i = threadIdx.x;
    if (i == 0) g_cnt = 0;
    if (i < HH) g_h[i] = prev_hidden[i];
}

// ---------------- SGEMM (fp32, register blocked, f32x2 packed accum) ----------------
// C[M,N] = act(A[M,K] @ B[K,N] + bias[N]); BM=128 BN=64 BK=16, 256 threads, 8x4/thread
__device__ __forceinline__ void sgemm_body(
    const float* __restrict__ A, const float* __restrict__ B,
    const float* __restrict__ bias, float* __restrict__ C,
    int M, int N, int K, bool relu)
{
    constexpr int BM = 128, BN = 64, BK = 16, TM = 8, TN = 4;
    __shared__ __align__(16) float As[BK][BM];
    __shared__ __align__(16) float Bs[BK][BN];

    const int tid = threadIdx.x;         // 256 threads
    const int tx = tid & 15;             // 16 col groups
    const int ty = tid >> 4;             // 16 row groups
    const int row0 = ty * TM;
    const int col0 = tx * TN;
    const int rowBase = blockIdx.y * BM;
    const int colBase = blockIdx.x * BN;

    // packed accumulators: row-pair i (rows 2i,2i+1), col j
    ull acc2[TM / 2][TN];
#pragma unroll
    for (int i = 0; i < TM / 2; i++)
#pragma unroll
        for (int j = 0; j < TN; j++) acc2[i][j] = 0ull;

    for (int k0 = 0; k0 < K; k0 += BK) {
        // Load A tile (128x16) -> transposed into As[BK][BM]
#pragma unroll
        for (int i = 0; i < 2; i++) {
            int idx = tid * 2 + i;             // 0..511
            int r = idx >> 2;                  // 0..127
            int c4 = (idx & 3) * 4;            // 0,4,8,12
            float4 v = *(const float4*)(A + (size_t)(rowBase + r) * K + k0 + c4);
            As[c4 + 0][r] = v.x;
            As[c4 + 1][r] = v.y;
            As[c4 + 2][r] = v.z;
            As[c4 + 3][r] = v.w;
        }
        // Load B tile (16x64)
        {
            int r = tid >> 4;                  // 0..15
            int c = (tid & 15) * 4;            // 0..60
            *(float4*)&Bs[r][c] = *(const float4*)(B + (size_t)(k0 + r) * N + colBase + c);
        }
        __syncthreads();

#pragma unroll
        for (int kk = 0; kk < BK; kk++) {
            // consecutive rows in As are adjacent -> direct 64-bit packed loads
            const ull* ap = (const ull*)&As[kk][row0];   // row0 multiple of 8 -> 32B aligned
            ull a01 = ap[0], a23 = ap[1], a45 = ap[2], a67 = ap[3];
            float4 b4 = *(float4*)&Bs[kk][col0];
            ull b0 = pk2(b4.x, b4.x), b1 = pk2(b4.y, b4.y);
            ull b2 = pk2(b4.z, b4.z), b3 = pk2(b4.w, b4.w);
            FMA2(acc2[0][0], a01, b0); FMA2(acc2[0][1], a01, b1);
            FMA2(acc2[0][2], a01, b2); FMA2(acc2[0][3], a01, b3);
            FMA2(acc2[1][0], a23, b0); FMA2(acc2[1][1], a23, b1);
            FMA2(acc2[1][2], a23, b2); FMA2(acc2[1][3], a23, b3);
            FMA2(acc2[2][0], a45, b0); FMA2(acc2[2][1], a45, b1);
            FMA2(acc2[2][2], a45, b2); FMA2(acc2[2][3], a45, b3);
            FMA2(acc2[3][0], a67, b0); FMA2(acc2[3][1], a67, b1);
            FMA2(acc2[3][2], a67, b2); FMA2(acc2[3][3], a67, b3);
        }
        __syncthreads();
    }

    // Epilogue
    float4 bv = *(const float4*)(bias + colBase + col0);
    float bb[TN] = {bv.x, bv.y, bv.z, bv.w};
#pragma unroll
    for (int i = 0; i < TM / 2; i++) {
        float2 c0 = upk2(acc2[i][0]);
        float2 c1 = upk2(acc2[i][1]);
        float2 c2 = upk2(acc2[i][2]);
        float2 c3 = upk2(acc2[i][3]);
        float lo[TN] = {c0.x + bb[0], c1.x + bb[1], c2.x + bb[2], c3.x + bb[3]};
        float hi[TN] = {c0.y + bb[0], c1.y + bb[1], c2.y + bb[2], c3.y + bb[3]};
        if (relu) {
#pragma unroll
            for (int j = 0; j < TN; j++) {
                lo[j] = fmaxf(lo[j], 0.f);
                hi[j] = fmaxf(hi[j], 0.f);
            }
        }
        float4 olo = {lo[0], lo[1], lo[2], lo[3]};
        float4 ohi = {hi[0], hi[1], hi[2], hi[3]};
        *(float4*)(C + (size_t)(rowBase + row0 + 2 * i) * N + colBase + col0) = olo;
        *(float4*)(C + (size_t)(rowBase + row0 + 2 * i + 1) * N + colBase + col0) = ohi;
    }
}

__global__ __launch_bounds__(256) void k_gemm1(const float* __restrict__ x,
                                               const float* __restrict__ W1,
                                               const float* __restrict__ b1) {
    sgemm_body(x, W1, b1, g_z1, TT, DD, DIN, true);
}
__global__ __launch_bounds__(256) void k_gemm2(const float* __restrict__ W2,
                                               const float* __restrict__ b2) {
    sgemm_body(g_z1, W2, b2, g_z2, TT, DD, DD, true);
}
__global__ __launch_bounds__(256) void k_gemm3(const float* __restrict__ Wg,
                                               const float* __restrict__ bg) {
    // bias = bg row 0 (input bias)
    sgemm_body(g_z2, Wg, bg, g_X, TT, H3, DD, false);
}

// ---------------- GRU sequential scan (persistent, counter-synced) ----------------
__global__ __launch_bounds__(GRU_THREADS, 1) void k_gru(
    const float* __restrict__ Ug,   // [512, 1536]
    const float* __restrict__ bg)   // [2, 1536]; row 1 = recurrent bias
{
    const int tid = threadIdx.x;       // 0..127
    const int g = tid >> 4;            // 0..7   (h index within chunk)
    const int s = tid & 15;            // 0..15  (k split)
    const int col = blockIdx.x * 8 + g;
    const bool leader = (s == 0);

    // Register-resident recurrent weights: 3 gates x 32 k-values, packed as f32x2
    ull w2[3][16];
#pragma unroll
    for (int q = 0; q < 3; q++) {
        const float* ugc = Ug + (size_t)q * HH + col;
#pragma unroll
        for (int m = 0; m < 16; m++) {
            float lo = ugc[(size_t)(s * 32 + 2 * m) * H3];
            float hi = ugc[(size_t)(s * 32 + 2 * m + 1) * H3];
            w2[q][m] = pk2(lo, hi);
        }
    }
    float br0 = 0.f, br1 = 0.f, br2 = 0.f;
    if (leader) {
        br0 = bg[H3 + col];
        br1 = bg[H3 + HH + col];
        br2 = bg[H3 + 2 * HH + col];
    }

    const float* xp = g_X + col;
    for (int t = 0; t < TT; t++) {
        // Prefetch input projections (independent of h) before the wait
        float xg0 = 0.f, xg1 = 0.f, xg2 = 0.f;
        if (leader) {
            xg0 = __ldcs(xp);
            xg1 = __ldcs(xp + HH);
            xg2 = __ldcs(xp + 2 * HH);
        }
        xp += H3;

        // Wait until all 64 CTAs have published h_t (single-line acquire poll)
        const int target = t * NCG;
        while (ld_acq(&g_cnt) < target) {}

        const float* hb = g_h + (t & 1) * HH;
        float hold = leader ? __ldcg(hb + col) : 0.f;

        // Load my 32-element k-slice of h as packed pairs (L2, 16B loads)
        ull h2[16];
        const ull* hp = (const ull*)(hb + s * 32);
#pragma unroll
        for (int i = 0; i < 8; i++) {
            asm volatile("ld.global.cg.v2.u64 {%0,%1},[%2];"
                         : "=l"(h2[2 * i]), "=l"(h2[2 * i + 1]) : "l"(hp + 2 * i));
        }

        // Packed partial matvec: 3 gate columns, 48 FFMA2
        ull a0 = 0ull, a1 = 0ull, a2 = 0ull;
#pragma unroll
        for (int m = 0; m < 16; m++) {
            FMA2(a0, h2[m], w2[0][m]);
            FMA2(a1, h2[m], w2[1][m]);
            FMA2(a2, h2[m], w2[2][m]);
        }
        float2 f0 = upk2(a0), f1 = upk2(a1), f2 = upk2(a2);
        float s0 = f0.x + f0.y, s1 = f1.x + f1.y, s2 = f2.x + f2.y;
#pragma unroll
        for (int off = 8; off >= 1; off >>= 1) {
            s0 += __shfl_xor_sync(0xffffffffu, s0, off);
            s1 += __shfl_xor_sync(0xffffffffu, s1, off);
            s2 += __shfl_xor_sync(0xffffffffu, s2, off);
        }

        if (leader) {
            float zt = 1.f / (1.f + __expf(-(xg0 + s0 + br0)));
            float rt = 1.f / (1.f + __expf(-(xg1 + s1 + br1)));
            float hh = 1.f / (1.f + __expf(-(xg2 + rt * (s2 + br2))));
            float hn = zt * hold + (1.f - zt) * hh;
            __stcg((float*)(g_h + ((t + 1) & 1) * HH + col), hn);
            __stcs(g_seq + (size_t)t * HH + col, hn);
        }
        __syncthreads();               // leaders' stores + all reads done
        if (tid == 0) red_rel_add(&g_cnt, 1);   // gpu-scope release publish
    }
}

// ---------------- Heads: policy softmax + value + hT ----------------
__global__ __launch_bounds__(256) void k_head(
    const float* __restrict__ Wp, const float* __restrict__ bp,
    const float* __restrict__ Wv, const float* __restrict__ bv,
    float* __restrict__ policy, float* __restrict__ value, float* __restrict__ hT)
{
    __shared__ float sWp[HH * AA];   // 36 KB
    __shared__ float sWv[HH];
    __shared__ float sbp[AA];

    const int tid = threadIdx.x;
    for (int i = tid; i < HH * AA; i += 256) sWp[i] = Wp[i];
    for (int i = tid; i < HH; i += 256) sWv[i] = Wv[i];
    if (tid < AA) sbp[tid] = bp[tid];
    __syncthreads();

    // hT = seq[T-1]
    if (blockIdx.x == 0) {
        for (int i = tid; i < HH; i += 256) hT[i] = g_seq[(size_t)(TT - 1) * HH + i];
    }

    const int warp = tid >> 5;
    const int lane = tid & 31;
    const int gwarp = blockIdx.x * 8 + warp;
    const int nwarps = gridDim.x * 8;
    const float bvv = bv[0];

    for (int row = gwarp; row < TT; row += nwarps) {
        float acc[AA + 1];
#pragma unroll
        for (int o = 0; o <= AA; o++) acc[o] = 0.f;

        const float* hrow = g_seq + (size_t)row * HH;
#pragma unroll 4
        for (int i = 0; i < HH / 32; i++) {
            int k = i * 32 + lane;
            float h = hrow[k];
            const float* wr = &sWp[k * AA];
#pragma unroll
            for (int o = 0; o < AA; o++) acc[o] = fmaf(h, wr[o], acc[o]);
            acc[AA] = fmaf(h, sWv[k], acc[AA]);
        }
#pragma unroll
        for (int off = 16; off >= 1; off >>= 1) {
#pragma unroll
            for (int o = 0; o <= AA; o++)
                acc[o] += __shfl_xor_sync(0xffffffffu, acc[o], off);
        }
        if (lane == 0) {
            float logits[AA];
            float mx = -1e30f;
#pragma unroll
            for (int o = 0; o < AA; o++) {
                logits[o] = acc[o] + sbp[o];
                mx = fmaxf(mx, logits[o]);
            }
            float sum = 0.f;
#pragma unroll
            for (int o = 0; o < AA; o++) {
                logits[o] = __expf(logits[o] - mx);
                sum += logits[o];
            }
            float inv = 1.f / sum;
            float* prow = policy + (size_t)row * AA;
#pragma unroll
            for (int o = 0; o < AA; o++) prow[o] = logits[o] * inv;
            value[row] = acc[AA] + bvv;
        }
    }
}

// ---------------- launch ----------------
extern "C" void kernel_launch(void* const* d_in, const int* in_sizes, int n_in,
                              void* d_out, int out_size) {
    const float* x    = (const float*)d_in[0];
    const float* prev = (const float*)d_in[1];
    const float* W1   = (const float*)d_in[2];
    const float* b1   = (const float*)d_in[3];
    const float* W2   = (const float*)d_in[4];
    const float* b2   = (const float*)d_in[5];
    const float* Wg   = (const float*)d_in[6];
    const float* Ug   = (const float*)d_in[7];
    const float* bg   = (const float*)d_in[8];
    const float* Wp   = (const float*)d_in[9];
    const float* bp   = (const float*)d_in[10];
    const float* Wv   = (const float*)d_in[11];
    const float* bv   = (const float*)d_in[12];

    float* out    = (float*)d_out;
    float* policy = out;                        // [T, A]
    float* value  = out + (size_t)TT * AA;      // [T, 1]
    float* hT     = out + (size_t)TT * AA + TT; // [1, H]

    k_init<<<1, 512>>>(prev);

    dim3 blk(256);
    k_gemm1<<<dim3(DD / 64, TT / 128), blk>>>(x, W1, b1);
    k_gemm2<<<dim3(DD / 64, TT / 128), blk>>>(W2, b2);
    k_gemm3<<<dim3(H3 / 64, TT / 128), blk>>>(Wg, bg);

    k_gru<<<NCG, GRU_THREADS>>>(Ug, bg);

    k_head<<<256, 256>>>(Wp, bp, Wv, bv, policy, value, hT);

    (void)in_sizes; (void)n_in; (void)out_size;
}

// round 3
// speedup vs baseline: 1.0674x; 1.0544x over previous
#include <cuda_runtime.h>
#include <cuda_bf16.h>

// Problem dims
#define TT 8192
#define DIN 2048
#define DD 512
#define HH 512
#define AA 18
#define H3 1536

// GRU persistent-kernel config
#define NCG 64         // CTAs
#define GRU_THREADS 128

typedef unsigned long long ull;

// ---------------- scratch (device globals; no allocation allowed) ----------------
__device__ float g_z1[(size_t)TT * DD];
__device__ float g_z2[(size_t)TT * DD];
__device__ float g_X[(size_t)TT * H3];
__device__ float g_seq[(size_t)TT * HH];
__device__ __align__(128) float g_h[2 * HH];
struct __align__(128) CntLine { int v; int pad[31]; };
__device__ CntLine g_cnt;   // isolated 128B line: polling traffic must not share a line

// ---------------- packed f32x2 helpers (sm_103a FFMA2) ----------------
__device__ __forceinline__ ull pk2(float lo, float hi) {
    ull r; asm("mov.b64 %0,{%1,%2};" : "=l"(r) : "f"(lo), "f"(hi)); return r;
}
__device__ __forceinline__ float2 upk2(ull v) {
    float2 r; asm("mov.b64 {%0,%1},%2;" : "=f"(r.x), "=f"(r.y) : "l"(v)); return r;
}
#define FMA2(d, a, b) asm("fma.rn.f32x2 %0,%1,%2,%0;" : "+l"(d) : "l"(a), "l"(b))

// ---------------- gpu-scope acquire/release primitives ----------------
__device__ __forceinline__ int ld_acq(const int* p) {
    int v; asm volatile("ld.acquire.gpu.global.s32 %0,[%1];" : "=r"(v) : "l"(p)); return v;
}
__device__ __forceinline__ void red_rel_add(int* p, int v) {
    asm volatile("red.release.gpu.global.add.s32 [%0],%1;" :: "l"(p), "r"(v) : "memory");
}

// ---------------- init ----------------
__global__ void k_init(const float* __restrict__ prev_hidden) {
    int i = threadIdx.x;
    if (i == 0) g_cnt.v = 0;
    if (i < HH) g_h[i] = prev_hidden[i];
}

// ---------------- SGEMM (fp32, register blocked, f32x2 packed accum) ----------------
// C[M,N] = act(A[M,K] @ B[K,N] + bias[N]); BM=128 BN=64 BK=16, 256 threads, 8x4/thread
__device__ __forceinline__ void sgemm_body(
    const float* __restrict__ A, const float* __restrict__ B,
    const float* __restrict__ bias, float* __restrict__ C,
    int M, int N, int K, bool relu)
{
    constexpr int BM = 128, BN = 64, BK = 16, TM = 8, TN = 4;
    __shared__ __align__(16) float As[BK][BM];
    __shared__ __align__(16) float Bs[BK][BN];

    const int tid = threadIdx.x;         // 256 threads
    const int tx = tid & 15;             // 16 col groups
    const int ty = tid >> 4;             // 16 row groups
    const int row0 = ty * TM;
    const int col0 = tx * TN;
    const int rowBase = blockIdx.y * BM;
    const int colBase = blockIdx.x * BN;

    // packed accumulators: row-pair i (rows 2i,2i+1), col j
    ull acc2[TM / 2][TN];
#pragma unroll
    for (int i = 0; i < TM / 2; i++)
#pragma unroll
        for (int j = 0; j < TN; j++) acc2[i][j] = 0ull;

    for (int k0 = 0; k0 < K; k0 += BK) {
        // Load A tile (128x16) -> transposed into As[BK][BM]
#pragma unroll
        for (int i = 0; i < 2; i++) {
            int idx = tid * 2 + i;             // 0..511
            int r = idx >> 2;                  // 0..127
            int c4 = (idx & 3) * 4;            // 0,4,8,12
            float4 v = *(const float4*)(A + (size_t)(rowBase + r) * K + k0 + c4);
            As[c4 + 0][r] = v.x;
            As[c4 + 1][r] = v.y;
            As[c4 + 2][r] = v.z;
            As[c4 + 3][r] = v.w;
        }
        // Load B tile (16x64)
        {
            int r = tid >> 4;                  // 0..15
            int c = (tid & 15) * 4;            // 0..60
            *(float4*)&Bs[r][c] = *(const float4*)(B + (size_t)(k0 + r) * N + colBase + c);
        }
        __syncthreads();

#pragma unroll
        for (int kk = 0; kk < BK; kk++) {
            // consecutive rows in As are adjacent -> direct 64-bit packed loads
            const ull* ap = (const ull*)&As[kk][row0];   // row0 multiple of 8 -> 32B aligned
            ull a01 = ap[0], a23 = ap[1], a45 = ap[2], a67 = ap[3];
            float4 b4 = *(float4*)&Bs[kk][col0];
            ull b0 = pk2(b4.x, b4.x), b1 = pk2(b4.y, b4.y);
            ull b2 = pk2(b4.z, b4.z), b3 = pk2(b4.w, b4.w);
            FMA2(acc2[0][0], a01, b0); FMA2(acc2[0][1], a01, b1);
            FMA2(acc2[0][2], a01, b2); FMA2(acc2[0][3], a01, b3);
            FMA2(acc2[1][0], a23, b0); FMA2(acc2[1][1], a23, b1);
            FMA2(acc2[1][2], a23, b2); FMA2(acc2[1][3], a23, b3);
            FMA2(acc2[2][0], a45, b0); FMA2(acc2[2][1], a45, b1);
            FMA2(acc2[2][2], a45, b2); FMA2(acc2[2][3], a45, b3);
            FMA2(acc2[3][0], a67, b0); FMA2(acc2[3][1], a67, b1);
            FMA2(acc2[3][2], a67, b2); FMA2(acc2[3][3], a67, b3);
        }
        __syncthreads();
    }

    // Epilogue
    float4 bv = *(const float4*)(bias + colBase + col0);
    float bb[TN] = {bv.x, bv.y, bv.z, bv.w};
#pragma unroll
    for (int i = 0; i < TM / 2; i++) {
        float2 c0 = upk2(acc2[i][0]);
        float2 c1 = upk2(acc2[i][1]);
        float2 c2 = upk2(acc2[i][2]);
        float2 c3 = upk2(acc2[i][3]);
        float lo[TN] = {c0.x + bb[0], c1.x + bb[1], c2.x + bb[2], c3.x + bb[3]};
        float hi[TN] = {c0.y + bb[0], c1.y + bb[1], c2.y + bb[2], c3.y + bb[3]};
        if (relu) {
#pragma unroll
            for (int j = 0; j < TN; j++) {
                lo[j] = fmaxf(lo[j], 0.f);
                hi[j] = fmaxf(hi[j], 0.f);
            }
        }
        float4 olo = {lo[0], lo[1], lo[2], lo[3]};
        float4 ohi = {hi[0], hi[1], hi[2], hi[3]};
        *(float4*)(C + (size_t)(rowBase + row0 + 2 * i) * N + colBase + col0) = olo;
        *(float4*)(C + (size_t)(rowBase + row0 + 2 * i + 1) * N + colBase + col0) = ohi;
    }
}

__global__ __launch_bounds__(256) void k_gemm1(const float* __restrict__ x,
                                               const float* __restrict__ W1,
                                               const float* __restrict__ b1) {
    sgemm_body(x, W1, b1, g_z1, TT, DD, DIN, true);
}
__global__ __launch_bounds__(256) void k_gemm2(const float* __restrict__ W2,
                                               const float* __restrict__ b2) {
    sgemm_body(g_z1, W2, b2, g_z2, TT, DD, DD, true);
}
__global__ __launch_bounds__(256) void k_gemm3(const float* __restrict__ Wg,
                                               const float* __restrict__ bg) {
    // bias = bg row 0 (input bias)
    sgemm_body(g_z2, Wg, bg, g_X, TT, H3, DD, false);
}

// ---------------- GRU sequential scan (persistent, counter-synced) ----------------
// Sync discipline: ONLY tid 0 of each CTA polls the global counter (64 pollers
// chip-wide on one isolated 128B line); everyone else waits at __syncthreads.
__global__ __launch_bounds__(GRU_THREADS, 1) void k_gru(
    const float* __restrict__ Ug,   // [512, 1536]
    const float* __restrict__ bg)   // [2, 1536]; row 1 = recurrent bias
{
    const int tid = threadIdx.x;       // 0..127
    const int g = tid >> 4;            // 0..7   (h index within chunk)
    const int s = tid & 15;            // 0..15  (k split)
    const int col = blockIdx.x * 8 + g;
    const bool leader = (s == 0);

    // Register-resident recurrent weights: 3 gates x 32 k-values, packed as f32x2
    ull w2[3][16];
#pragma unroll
    for (int q = 0; q < 3; q++) {
        const float* ugc = Ug + (size_t)q * HH + col;
#pragma unroll
        for (int m = 0; m < 16; m++) {
            float lo = ugc[(size_t)(s * 32 + 2 * m) * H3];
            float hi = ugc[(size_t)(s * 32 + 2 * m + 1) * H3];
            w2[q][m] = pk2(lo, hi);
        }
    }
    float br0 = 0.f, br1 = 0.f, br2 = 0.f;
    if (leader) {
        br0 = bg[H3 + col];
        br1 = bg[H3 + HH + col];
        br2 = bg[H3 + 2 * HH + col];
    }

    const float* xp = g_X + col;
    for (int t = 0; t < TT; t++) {
        // Prefetch input projections (independent of h) before the wait
        float xg0 = 0.f, xg1 = 0.f, xg2 = 0.f;
        if (leader) {
            xg0 = __ldcs(xp);
            xg1 = __ldcs(xp + HH);
            xg2 = __ldcs(xp + 2 * HH);
        }
        xp += H3;

        // Single-poller wait: all 64 CTAs have published h_t when cnt >= t*64
        if (tid == 0) {
            const int target = t * NCG;
            while (ld_acq(&g_cnt.v) < target) {}
        }
        __syncthreads();

        const float* hb = g_h + (t & 1) * HH;
        float hold = leader ? __ldcg(hb + col) : 0.f;

        // Load my 32-element k-slice of h as packed pairs (L2, 16B loads)
        ull h2[16];
        const ull* hp = (const ull*)(hb + s * 32);
#pragma unroll
        for (int i = 0; i < 8; i++) {
            asm volatile("ld.global.cg.v2.u64 {%0,%1},[%2];"
                         : "=l"(h2[2 * i]), "=l"(h2[2 * i + 1]) : "l"(hp + 2 * i));
        }

        // Packed partial matvec: 3 gate columns, 48 FFMA2
        ull a0 = 0ull, a1 = 0ull, a2 = 0ull;
#pragma unroll
        for (int m = 0; m < 16; m++) {
            FMA2(a0, h2[m], w2[0][m]);
            FMA2(a1, h2[m], w2[1][m]);
            FMA2(a2, h2[m], w2[2][m]);
        }
        float2 f0 = upk2(a0), f1 = upk2(a1), f2 = upk2(a2);
        float s0 = f0.x + f0.y, s1 = f1.x + f1.y, s2 = f2.x + f2.y;
#pragma unroll
        for (int off = 8; off >= 1; off >>= 1) {
            s0 += __shfl_xor_sync(0xffffffffu, s0, off);
            s1 += __shfl_xor_sync(0xffffffffu, s1, off);
            s2 += __shfl_xor_sync(0xffffffffu, s2, off);
        }

        if (leader) {
            float zt = 1.f / (1.f + __expf(-(xg0 + s0 + br0)));
            float rt = 1.f / (1.f + __expf(-(xg1 + s1 + br1)));
            float hh = 1.f / (1.f + __expf(-(xg2 + rt * (s2 + br2))));
            float hn = zt * hold + (1.f - zt) * hh;
            __stcg((float*)(g_h + ((t + 1) & 1) * HH + col), hn);
            __stcs(g_seq + (size_t)t * HH + col, hn);
        }
        __syncthreads();               // leaders' stores + all reads done
        if (tid == 0) red_rel_add(&g_cnt.v, 1);   // gpu-scope release publish
    }
}

// ---------------- Heads: policy softmax + value + hT ----------------
__global__ __launch_bounds__(256) void k_head(
    const float* __restrict__ Wp, const float* __restrict__ bp,
    const float* __restrict__ Wv, const float* __restrict__ bv,
    float* __restrict__ policy, float* __restrict__ value, float* __restrict__ hT)
{
    __shared__ float sWp[HH * AA];   // 36 KB
    __shared__ float sWv[HH];
    __shared__ float sbp[AA];

    const int tid = threadIdx.x;
    for (int i = tid; i < HH * AA; i += 256) sWp[i] = Wp[i];
    for (int i = tid; i < HH; i += 256) sWv[i] = Wv[i];
    if (tid < AA) sbp[tid] = bp[tid];
    __syncthreads();

    // hT = seq[T-1]
    if (blockIdx.x == 0) {
        for (int i = tid; i < HH; i += 256) hT[i] = g_seq[(size_t)(TT - 1) * HH + i];
    }

    const int warp = tid >> 5;
    const int lane = tid & 31;
    const int gwarp = blockIdx.x * 8 + warp;
    const int nwarps = gridDim.x * 8;
    const float bvv = bv[0];

    for (int row = gwarp; row < TT; row += nwarps) {
        float acc[AA + 1];
#pragma unroll
        for (int o = 0; o <= AA; o++) acc[o] = 0.f;

        const float* hrow = g_seq + (size_t)row * HH;
#pragma unroll 4
        for (int i = 0; i < HH / 32; i++) {
            int k = i * 32 + lane;
            float h = hrow[k];
            const float* wr = &sWp[k * AA];
#pragma unroll
            for (int o = 0; o < AA; o++) acc[o] = fmaf(h, wr[o], acc[o]);
            acc[AA] = fmaf(h, sWv[k], acc[AA]);
        }
#pragma unroll
        for (int off = 16; off >= 1; off >>= 1) {
#pragma unroll
            for (int o = 0; o <= AA; o++)
                acc[o] += __shfl_xor_sync(0xffffffffu, acc[o], off);
        }
        if (lane == 0) {
            float logits[AA];
            float mx = -1e30f;
#pragma unroll
            for (int o = 0; o < AA; o++) {
                logits[o] = acc[o] + sbp[o];
                mx = fmaxf(mx, logits[o]);
            }
            float sum = 0.f;
#pragma unroll
            for (int o = 0; o < AA; o++) {
                logits[o] = __expf(logits[o] - mx);
                sum += logits[o];
            }
            float inv = 1.f / sum;
            float* prow = policy + (size_t)row * AA;
#pragma unroll
            for (int o = 0; o < AA; o++) prow[o] = logits[o] * inv;
            value[row] = acc[AA] + bvv;
        }
    }
}

// ---------------- launch ----------------
extern "C" void kernel_launch(void* const* d_in, const int* in_sizes, int n_in,
                              void* d_out, int out_size) {
    const float* x    = (const float*)d_in[0];
    const float* prev = (const float*)d_in[1];
    const float* W1   = (const float*)d_in[2];
    const float* b1   = (const float*)d_in[3];
    const float* W2   = (const float*)d_in[4];
    const float* b2   = (const float*)d_in[5];
    const float* Wg   = (const float*)d_in[6];
    const float* Ug   = (const float*)d_in[7];
    const float* bg   = (const float*)d_in[8];
    const float* Wp   = (const float*)d_in[9];
    const float* bp   = (const float*)d_in[10];
    const float* Wv   = (const float*)d_in[11];
    const float* bv   = (const float*)d_in[12];

    float* out    = (float*)d_out;
    float* policy = out;                        // [T, A]
    float* value  = out + (size_t)TT * AA;      // [T, 1]
    float* hT     = out + (size_t)TT * AA + TT; // [1, H]

    k_init<<<1, 512>>>(prev);

    dim3 blk(256);
    k_gemm1<<<dim3(DD / 64, TT / 128), blk>>>(x, W1, b1);
    k_gemm2<<<dim3(DD / 64, TT / 128), blk>>>(W2, b2);
    k_gemm3<<<dim3(H3 / 64, TT / 128), blk>>>(Wg, bg);

    k_gru<<<NCG, GRU_THREADS>>>(Ug, bg);

    k_head<<<256, 256>>>(Wp, bp, Wv, bv, policy, value, hT);

    (void)in_sizes; (void)n_in; (void)out_size;
}

// round 4
// speedup vs baseline: 2.1146x; 1.9812x over previous
#include <cuda_runtime.h>
#include <cuda_bf16.h>

// Problem dims
#define TT 8192
#define DIN 2048
#define DD 512
#define HH 512
#define AA 18
#define H3 1536

// GRU persistent-kernel config
#define NCG 32         // CTAs
#define GRU_THREADS 256
#define COLS_PER_CTA 16

typedef unsigned long long ull;

// ---------------- scratch (device globals; no allocation allowed) ----------------
__device__ float g_z1[(size_t)TT * DD];
__device__ float g_z2[(size_t)TT * DD];
__device__ float g_X[(size_t)TT * H3];
__device__ float g_seq[(size_t)TT * HH];
__device__ __align__(128) float g_h[2 * HH];
struct __align__(128) CntLine { int v; int pad[31]; };
__device__ CntLine g_cnt;   // isolated 128B line

// ---------------- packed f32x2 helpers (sm_103a FFMA2) ----------------
__device__ __forceinline__ ull pk2(float lo, float hi) {
    ull r; asm("mov.b64 %0,{%1,%2};" : "=l"(r) : "f"(lo), "f"(hi)); return r;
}
__device__ __forceinline__ float2 upk2(ull v) {
    float2 r; asm("mov.b64 {%0,%1},%2;" : "=f"(r.x), "=f"(r.y) : "l"(v)); return r;
}
#define FMA2(d, a, b) asm("fma.rn.f32x2 %0,%1,%2,%0;" : "+l"(d) : "l"(a), "l"(b))

// ---------------- gpu-scope acquire/release primitives ----------------
__device__ __forceinline__ int ld_acq(const int* p) {
    int v; asm volatile("ld.acquire.gpu.global.s32 %0,[%1];" : "=r"(v) : "l"(p)); return v;
}
__device__ __forceinline__ void red_rel_add(int* p, int v) {
    asm volatile("red.release.gpu.global.add.s32 [%0],%1;" :: "l"(p), "r"(v) : "memory");
}

// ---------------- init ----------------
__global__ void k_init(const float* __restrict__ prev_hidden) {
    int i = threadIdx.x;
    if (i == 0) g_cnt.v = 0;
    if (i < HH) g_h[i] = prev_hidden[i];
}

// ---------------- SGEMM (fp32, register blocked, f32x2 packed accum) ----------------
__device__ __forceinline__ void sgemm_body(
    const float* __restrict__ A, const float* __restrict__ B,
    const float* __restrict__ bias, float* __restrict__ C,
    int M, int N, int K, bool relu)
{
    constexpr int BM = 128, BN = 64, BK = 16, TM = 8, TN = 4;
    __shared__ __align__(16) float As[BK][BM];
    __shared__ __align__(16) float Bs[BK][BN];

    const int tid = threadIdx.x;
    const int tx = tid & 15;
    const int ty = tid >> 4;
    const int row0 = ty * TM;
    const int col0 = tx * TN;
    const int rowBase = blockIdx.y * BM;
    const int colBase = blockIdx.x * BN;

    ull acc2[TM / 2][TN];
#pragma unroll
    for (int i = 0; i < TM / 2; i++)
#pragma unroll
        for (int j = 0; j < TN; j++) acc2[i][j] = 0ull;

    for (int k0 = 0; k0 < K; k0 += BK) {
#pragma unroll
        for (int i = 0; i < 2; i++) {
            int idx = tid * 2 + i;
            int r = idx >> 2;
            int c4 = (idx & 3) * 4;
            float4 v = *(const float4*)(A + (size_t)(rowBase + r) * K + k0 + c4);
            As[c4 + 0][r] = v.x;
            As[c4 + 1][r] = v.y;
            As[c4 + 2][r] = v.z;
            As[c4 + 3][r] = v.w;
        }
        {
            int r = tid >> 4;
            int c = (tid & 15) * 4;
            *(float4*)&Bs[r][c] = *(const float4*)(B + (size_t)(k0 + r) * N + colBase + c);
        }
        __syncthreads();

#pragma unroll
        for (int kk = 0; kk < BK; kk++) {
            const ull* ap = (const ull*)&As[kk][row0];
            ull a01 = ap[0], a23 = ap[1], a45 = ap[2], a67 = ap[3];
            float4 b4 = *(float4*)&Bs[kk][col0];
            ull b0 = pk2(b4.x, b4.x), b1 = pk2(b4.y, b4.y);
            ull b2 = pk2(b4.z, b4.z), b3 = pk2(b4.w, b4.w);
            FMA2(acc2[0][0], a01, b0); FMA2(acc2[0][1], a01, b1);
            FMA2(acc2[0][2], a01, b2); FMA2(acc2[0][3], a01, b3);
            FMA2(acc2[1][0], a23, b0); FMA2(acc2[1][1], a23, b1);
            FMA2(acc2[1][2], a23, b2); FMA2(acc2[1][3], a23, b3);
            FMA2(acc2[2][0], a45, b0); FMA2(acc2[2][1], a45, b1);
            FMA2(acc2[2][2], a45, b2); FMA2(acc2[2][3], a45, b3);
            FMA2(acc2[3][0], a67, b0); FMA2(acc2[3][1], a67, b1);
            FMA2(acc2[3][2], a67, b2); FMA2(acc2[3][3], a67, b3);
        }
        __syncthreads();
    }

    float4 bv = *(const float4*)(bias + colBase + col0);
    float bb[TN] = {bv.x, bv.y, bv.z, bv.w};
#pragma unroll
    for (int i = 0; i < TM / 2; i++) {
        float2 c0 = upk2(acc2[i][0]);
        float2 c1 = upk2(acc2[i][1]);
        float2 c2 = upk2(acc2[i][2]);
        float2 c3 = upk2(acc2[i][3]);
        float lo[TN] = {c0.x + bb[0], c1.x + bb[1], c2.x + bb[2], c3.x + bb[3]};
        float hi[TN] = {c0.y + bb[0], c1.y + bb[1], c2.y + bb[2], c3.y + bb[3]};
        if (relu) {
#pragma unroll
            for (int j = 0; j < TN; j++) {
                lo[j] = fmaxf(lo[j], 0.f);
                hi[j] = fmaxf(hi[j], 0.f);
            }
        }
        float4 olo = {lo[0], lo[1], lo[2], lo[3]};
        float4 ohi = {hi[0], hi[1], hi[2], hi[3]};
        *(float4*)(C + (size_t)(rowBase + row0 + 2 * i) * N + colBase + col0) = olo;
        *(float4*)(C + (size_t)(rowBase + row0 + 2 * i + 1) * N + colBase + col0) = ohi;
    }
}

__global__ __launch_bounds__(256) void k_gemm1(const float* __restrict__ x,
                                               const float* __restrict__ W1,
                                               const float* __restrict__ b1) {
    sgemm_body(x, W1, b1, g_z1, TT, DD, DIN, true);
}
__global__ __launch_bounds__(256) void k_gemm2(const float* __restrict__ W2,
                                               const float* __restrict__ b2) {
    sgemm_body(g_z1, W2, b2, g_z2, TT, DD, DD, true);
}
__global__ __launch_bounds__(256) void k_gemm3(const float* __restrict__ Wg,
                                               const float* __restrict__ bg) {
    sgemm_body(g_z2, Wg, bg, g_X, TT, H3, DD, false);
}

// ---------------- GRU sequential scan (persistent, smem-staged h) ----------------
// 32 CTAs x 256 threads. Thread (g,s): g=tid>>4 -> column cta*16+g; s=tid&15 ->
// interleaved k-split owning ull-pairs {s, s+16, ..., s+240} (k = 2p, 2p+1).
// Each step: h is loaded from L2 ONCE per CTA into smem (2KB), then consumed
// via conflict-free LDS.64 — global h traffic is 64KB/step instead of 1MB.
__global__ __launch_bounds__(GRU_THREADS, 1) void k_gru(
    const float* __restrict__ Ug,   // [512, 1536]
    const float* __restrict__ bg)   // [2, 1536]; row 1 = recurrent bias
{
    const int tid = threadIdx.x;       // 0..255
    const int g = tid >> 4;            // 0..15  (column within CTA)
    const int s = tid & 15;            // 0..15  (interleaved k split)
    const int col = blockIdx.x * COLS_PER_CTA + g;
    const bool leader = (s == 0);

    __shared__ __align__(16) float sh_h[HH];

    // Register-resident recurrent weights, packed f32x2, in interleaved order:
    // j-th pair for this thread is ull-pair p = s + 16*j -> k = 2p, 2p+1
    ull w2[3][16];
#pragma unroll
    for (int q = 0; q < 3; q++) {
        const float* ugc = Ug + (size_t)q * HH + col;
#pragma unroll
        for (int j = 0; j < 16; j++) {
            int k0 = 2 * (s + 16 * j);
            w2[q][j] = pk2(ugc[(size_t)k0 * H3], ugc[(size_t)(k0 + 1) * H3]);
        }
    }
    float br0 = 0.f, br1 = 0.f, br2 = 0.f;
    if (leader) {
        br0 = bg[H3 + col];
        br1 = bg[H3 + HH + col];
        br2 = bg[H3 + 2 * HH + col];
    }

    const float* xp = g_X + col;
    for (int t = 0; t < TT; t++) {
        // Prefetch input projections (independent of h) before the wait
        float xg0 = 0.f, xg1 = 0.f, xg2 = 0.f;
        if (leader) {
            xg0 = __ldcs(xp);
            xg1 = __ldcs(xp + HH);
            xg2 = __ldcs(xp + 2 * HH);
        }
        xp += H3;

        // Single-poller wait: all CTAs have published h_t when cnt >= t*NCG
        if (tid == 0) {
            const int target = t * NCG;
            while (ld_acq(&g_cnt.v) < target) {}
        }
        __syncthreads();

        // Stage h_t: one pass global->smem (128 threads x float4 = 2KB)
        const float* hb = g_h + (t & 1) * HH;
        if (tid < 128) {
            float4 v = __ldcg((const float4*)(hb) + tid);
            *((float4*)sh_h + tid) = v;
        }
        __syncthreads();

        float hold = leader ? sh_h[col] : 0.f;

        // Conflict-free LDS.64: pair p = s + 16*j (lanes 0..15 hit distinct banks)
        const ull* shu = (const ull*)sh_h;
        ull a0 = 0ull, a1 = 0ull, a2 = 0ull;
#pragma unroll
        for (int j = 0; j < 16; j++) {
            ull h2 = shu[s + 16 * j];
            FMA2(a0, h2, w2[0][j]);
            FMA2(a1, h2, w2[1][j]);
            FMA2(a2, h2, w2[2][j]);
        }
        float2 f0 = upk2(a0), f1 = upk2(a1), f2 = upk2(a2);
        float s0 = f0.x + f0.y, s1 = f1.x + f1.y, s2 = f2.x + f2.y;
#pragma unroll
        for (int off = 8; off >= 1; off >>= 1) {
            s0 += __shfl_xor_sync(0xffffffffu, s0, off);
            s1 += __shfl_xor_sync(0xffffffffu, s1, off);
            s2 += __shfl_xor_sync(0xffffffffu, s2, off);
        }

        if (leader) {
            float zt = 1.f / (1.f + __expf(-(xg0 + s0 + br0)));
            float rt = 1.f / (1.f + __expf(-(xg1 + s1 + br1)));
            float hh = 1.f / (1.f + __expf(-(xg2 + rt * (s2 + br2))));
            float hn = zt * hold + (1.f - zt) * hh;
            __stcg((float*)(g_h + ((t + 1) & 1) * HH + col), hn);
            __stcs(g_seq + (size_t)t * HH + col, hn);
        }
        __syncthreads();               // leaders' stores + smem reads done
        if (tid == 0) red_rel_add(&g_cnt.v, 1);   // gpu-scope release publish
    }
}

// ---------------- Heads: policy softmax + value + hT ----------------
__global__ __launch_bounds__(256) void k_head(
    const float* __restrict__ Wp, const float* __restrict__ bp,
    const float* __restrict__ Wv, const float* __restrict__ bv,
    float* __restrict__ policy, float* __restrict__ value, float* __restrict__ hT)
{
    __shared__ float sWp[HH * AA];   // 36 KB
    __shared__ float sWv[HH];
    __shared__ float sbp[AA];

    const int tid = threadIdx.x;
    for (int i = tid; i < HH * AA; i += 256) sWp[i] = Wp[i];
    for (int i = tid; i < HH; i += 256) sWv[i] = Wv[i];
    if (tid < AA) sbp[tid] = bp[tid];
    __syncthreads();

    if (blockIdx.x == 0) {
        for (int i = tid; i < HH; i += 256) hT[i] = g_seq[(size_t)(TT - 1) * HH + i];
    }

    const int warp = tid >> 5;
    const int lane = tid & 31;
    const int gwarp = blockIdx.x * 8 + warp;
    const int nwarps = gridDim.x * 8;
    const float bvv = bv[0];

    for (int row = gwarp; row < TT; row += nwarps) {
        float acc[AA + 1];
#pragma unroll
        for (int o = 0; o <= AA; o++) acc[o] = 0.f;

        const float* hrow = g_seq + (size_t)row * HH;
#pragma unroll 4
        for (int i = 0; i < HH / 32; i++) {
            int k = i * 32 + lane;
            float h = hrow[k];
            const float* wr = &sWp[k * AA];
#pragma unroll
            for (int o = 0; o < AA; o++) acc[o] = fmaf(h, wr[o], acc[o]);
            acc[AA] = fmaf(h, sWv[k], acc[AA]);
        }
#pragma unroll
        for (int off = 16; off >= 1; off >>= 1) {
#pragma unroll
            for (int o = 0; o <= AA; o++)
                acc[o] += __shfl_xor_sync(0xffffffffu, acc[o], off);
        }
        if (lane == 0) {
            float logits[AA];
            float mx = -1e30f;
#pragma unroll
            for (int o = 0; o < AA; o++) {
                logits[o] = acc[o] + sbp[o];
                mx = fmaxf(mx, logits[o]);
            }
            float sum = 0.f;
#pragma unroll
            for (int o = 0; o < AA; o++) {
                logits[o] = __expf(logits[o] - mx);
                sum += logits[o];
            }
            float inv = 1.f / sum;
            float* prow = policy + (size_t)row * AA;
#pragma unroll
            for (int o = 0; o < AA; o++) prow[o] = logits[o] * inv;
            value[row] = acc[AA] + bvv;
        }
    }
}

// ---------------- launch ----------------
extern "C" void kernel_launch(void* const* d_in, const int* in_sizes, int n_in,
                              void* d_out, int out_size) {
    const float* x    = (const float*)d_in[0];
    const float* prev = (const float*)d_in[1];
    const float* W1   = (const float*)d_in[2];
    const float* b1   = (const float*)d_in[3];
    const float* W2   = (const float*)d_in[4];
    const float* b2   = (const float*)d_in[5];
    const float* Wg   = (const float*)d_in[6];
    const float* Ug   = (const float*)d_in[7];
    const float* bg   = (const float*)d_in[8];
    const float* Wp   = (const float*)d_in[9];
    const float* bp   = (const float*)d_in[10];
    const float* Wv   = (const float*)d_in[11];
    const float* bv   = (const float*)d_in[12];

    float* out    = (float*)d_out;
    float* policy = out;                        // [T, A]
    float* value  = out + (size_t)TT * AA;      // [T, 1]
    float* hT     = out + (size_t)TT * AA + TT; // [1, H]

    k_init<<<1, 512>>>(prev);

    dim3 blk(256);
    k_gemm1<<<dim3(DD / 64, TT / 128), blk>>>(x, W1, b1);
    k_gemm2<<<dim3(DD / 64, TT / 128), blk>>>(W2, b2);
    k_gemm3<<<dim3(H3 / 64, TT / 128), blk>>>(Wg, bg);

    k_gru<<<NCG, GRU_THREADS>>>(Ug, bg);

    k_head<<<256, 256>>>(Wp, bp, Wv, bv, policy, value, hT);

    (void)in_sizes; (void)n_in; (void)out_size;
}

// round 6
// speedup vs baseline: 2.3051x; 1.0901x over previous
#include <cuda_runtime.h>
#include <cuda_bf16.h>

// Problem dims
#define TT 8192
#define DIN 2048
#define DD 512
#define HH 512
#define AA 18
#define H3 1536

// GRU persistent-kernel config
#define NCG 32         // CTAs
#define GRU_THREADS 256
#define COLS_PER_CTA 16
#define RING 4         // h-exchange ring depth

typedef unsigned long long ull;

// ---------------- scratch (device globals; no allocation allowed) ----------------
__device__ float g_z1[(size_t)TT * DD];
__device__ float g_z2[(size_t)TT * DD];
__device__ float g_X[(size_t)TT * H3];
__device__ float g_seq[(size_t)TT * HH];
// h exchange ring: packed (value:f32 bits high 32 | tag:step low 32)
__device__ __align__(128) ull g_hp[RING][HH];

// ---------------- packed f32x2 helpers (sm_103a FFMA2) ----------------
__device__ __forceinline__ ull pk2(float lo, float hi) {
    ull r; asm("mov.b64 %0,{%1,%2};" : "=l"(r) : "f"(lo), "f"(hi)); return r;
}
__device__ __forceinline__ float2 upk2(ull v) {
    float2 r; asm("mov.b64 {%0,%1},%2;" : "=f"(r.x), "=f"(r.y) : "l"(v)); return r;
}
#define FMA2(d, a, b) asm("fma.rn.f32x2 %0,%1,%2,%0;" : "+l"(d) : "l"(a), "l"(b))

// ---------------- morally-strong relaxed 64-bit atomics (single-copy atomic) ----
__device__ __forceinline__ ull ld_rlx64(const ull* p) {
    ull v; asm volatile("ld.relaxed.gpu.global.b64 %0,[%1];" : "=l"(v) : "l"(p)); return v;
}
__device__ __forceinline__ void st_rlx64(ull* p, ull v) {
    asm volatile("st.relaxed.gpu.global.b64 [%0],%1;" :: "l"(p), "l"(v) : "memory");
}

// ---------------- init ----------------
__global__ void k_init(const float* __restrict__ prev_hidden) {
    int i = threadIdx.x;
    if (i < HH) {
        // slot 0 holds h_0 with tag 0; other slots poisoned (tag can never match)
        g_hp[0][i] = ((ull)__float_as_uint(prev_hidden[i]) << 32) | 0u;
        g_hp[1][i] = 0x0000000080000000ull;
        g_hp[2][i] = 0x0000000080000001ull;
        g_hp[3][i] = 0x0000000080000002ull;
    }
}

// ---------------- SGEMM (fp32, register blocked, f32x2 packed accum) ----------------
__device__ __forceinline__ void sgemm_body(
    const float* __restrict__ A, const float* __restrict__ B,
    const float* __restrict__ bias, float* __restrict__ C,
    int M, int N, int K, bool relu)
{
    constexpr int BM = 128, BN = 64, BK = 16, TM = 8, TN = 4;
    __shared__ __align__(16) float As[BK][BM];
    __shared__ __align__(16) float Bs[BK][BN];

    const int tid = threadIdx.x;
    const int tx = tid & 15;
    const int ty = tid >> 4;
    const int row0 = ty * TM;
    const int col0 = tx * TN;
    const int rowBase = blockIdx.y * BM;
    const int colBase = blockIdx.x * BN;

    ull acc2[TM / 2][TN];
#pragma unroll
    for (int i = 0; i < TM / 2; i++)
#pragma unroll
        for (int j = 0; j < TN; j++) acc2[i][j] = 0ull;

    for (int k0 = 0; k0 < K; k0 += BK) {
#pragma unroll
        for (int i = 0; i < 2; i++) {
            int idx = tid * 2 + i;
            int r = idx >> 2;
            int c4 = (idx & 3) * 4;
            float4 v = *(const float4*)(A + (size_t)(rowBase + r) * K + k0 + c4);
            As[c4 + 0][r] = v.x;
            As[c4 + 1][r] = v.y;
            As[c4 + 2][r] = v.z;
            As[c4 + 3][r] = v.w;
        }
        {
            int r = tid >> 4;
            int c = (tid & 15) * 4;
            *(float4*)&Bs[r][c] = *(const float4*)(B + (size_t)(k0 + r) * N + colBase + c);
        }
        __syncthreads();

#pragma unroll
        for (int kk = 0; kk < BK; kk++) {
            const ull* ap = (const ull*)&As[kk][row0];
            ull a01 = ap[0], a23 = ap[1], a45 = ap[2], a67 = ap[3];
            float4 b4 = *(float4*)&Bs[kk][col0];
            ull b0 = pk2(b4.x, b4.x), b1 = pk2(b4.y, b4.y);
            ull b2 = pk2(b4.z, b4.z), b3 = pk2(b4.w, b4.w);
            FMA2(acc2[0][0], a01, b0); FMA2(acc2[0][1], a01, b1);
            FMA2(acc2[0][2], a01, b2); FMA2(acc2[0][3], a01, b3);
            FMA2(acc2[1][0], a23, b0); FMA2(acc2[1][1], a23, b1);
            FMA2(acc2[1][2], a23, b2); FMA2(acc2[1][3], a23, b3);
            FMA2(acc2[2][0], a45, b0); FMA2(acc2[2][1], a45, b1);
            FMA2(acc2[2][2], a45, b2); FMA2(acc2[2][3], a45, b3);
            FMA2(acc2[3][0], a67, b0); FMA2(acc2[3][1], a67, b1);
            FMA2(acc2[3][2], a67, b2); FMA2(acc2[3][3], a67, b3);
        }
        __syncthreads();
    }

    float4 bv = *(const float4*)(bias + colBase + col0);
    float bb[TN] = {bv.x, bv.y, bv.z, bv.w};
#pragma unroll
    for (int i = 0; i < TM / 2; i++) {
        float2 c0 = upk2(acc2[i][0]);
        float2 c1 = upk2(acc2[i][1]);
        float2 c2 = upk2(acc2[i][2]);
        float2 c3 = upk2(acc2[i][3]);
        float lo[TN] = {c0.x + bb[0], c1.x + bb[1], c2.x + bb[2], c3.x + bb[3]};
        float hi[TN] = {c0.y + bb[0], c1.y + bb[1], c2.y + bb[2], c3.y + bb[3]};
        if (relu) {
#pragma unroll
            for (int j = 0; j < TN; j++) {
                lo[j] = fmaxf(lo[j], 0.f);
                hi[j] = fmaxf(hi[j], 0.f);
            }
        }
        float4 olo = {lo[0], lo[1], lo[2], lo[3]};
        float4 ohi = {hi[0], hi[1], hi[2], hi[3]};
        *(float4*)(C + (size_t)(rowBase + row0 + 2 * i) * N + colBase + col0) = olo;
        *(float4*)(C + (size_t)(rowBase + row0 + 2 * i + 1) * N + colBase + col0) = ohi;
    }
}

__global__ __launch_bounds__(256) void k_gemm1(const float* __restrict__ x,
                                               const float* __restrict__ W1,
                                               const float* __restrict__ b1) {
    sgemm_body(x, W1, b1, g_z1, TT, DD, DIN, true);
}
__global__ __launch_bounds__(256) void k_gemm2(const float* __restrict__ W2,
                                               const float* __restrict__ b2) {
    sgemm_body(g_z1, W2, b2, g_z2, TT, DD, DD, true);
}
__global__ __launch_bounds__(256) void k_gemm3(const float* __restrict__ Wg,
                                               const float* __restrict__ bg) {
    sgemm_body(g_z2, Wg, bg, g_X, TT, H3, DD, false);
}

// ---------------- GRU sequential scan (persistent, data-as-flag) ----------------
// 32 CTAs x 256 threads. Column c of h_t lives in g_hp[t % 4][c] as an 8-byte
// packed word (value<<32 | tag=t), written/read with RELAXED GPU-SCOPE ATOMICS
// (morally strong -> single-copy atomic; tag certifies value, no fences).
// Lockstep dependency (staging t requires every CTA's tag-t word, which
// requires every CTA to have fully staged t-1) bounds CTA skew to one step,
// so a 4-deep ring can never overwrite a live slot.
__global__ __launch_bounds__(GRU_THREADS, 1) void k_gru(
    const float* __restrict__ Ug,   // [512, 1536]
    const float* __restrict__ bg)   // [2, 1536]; row 1 = recurrent bias
{
    const int tid = threadIdx.x;       // 0..255
    const int g = tid >> 4;            // 0..15  (column within CTA)
    const int s = tid & 15;            // 0..15  (interleaved k split)
    const int col = blockIdx.x * COLS_PER_CTA + g;
    const bool leader = (s == 0);

    __shared__ __align__(16) float sh_h[2][HH];  // double-buffered staging

    // Register-resident recurrent weights, packed f32x2, interleaved order:
    // j-th pair for this thread is ull-pair p = s + 16*j -> k = 2p, 2p+1
    ull w2[3][16];
#pragma unroll
    for (int q = 0; q < 3; q++) {
        const float* ugc = Ug + (size_t)q * HH + col;
#pragma unroll
        for (int j = 0; j < 16; j++) {
            int k0 = 2 * (s + 16 * j);
            w2[q][j] = pk2(ugc[(size_t)k0 * H3], ugc[(size_t)(k0 + 1) * H3]);
        }
    }
    float br0 = 0.f, br1 = 0.f, br2 = 0.f;
    if (leader) {
        br0 = bg[H3 + col];
        br1 = bg[H3 + HH + col];
        br2 = bg[H3 + 2 * HH + col];
    }

    // X projections: double-buffered in registers (DRAM latency off the path)
    const float* xp = g_X + col;
    float xg0 = 0.f, xg1 = 0.f, xg2 = 0.f;
    if (leader) {
        xg0 = __ldcs(xp);
        xg1 = __ldcs(xp + HH);
        xg2 = __ldcs(xp + 2 * HH);
    }

    for (int t = 0; t < TT; t++) {
        // ---- stage h_t from ring slot t%4: poll until tag == t ----
        const ull* bp = g_hp[t & (RING - 1)];
        ull v1 = ld_rlx64(bp + tid);
        ull v2 = ld_rlx64(bp + tid + 256);
        while ((int)(unsigned)v1 != t) v1 = ld_rlx64(bp + tid);
        while ((int)(unsigned)v2 != t) v2 = ld_rlx64(bp + tid + 256);
        float* sh = sh_h[t & 1];
        sh[tid] = __uint_as_float((unsigned)(v1 >> 32));
        sh[tid + 256] = __uint_as_float((unsigned)(v2 >> 32));
        __syncthreads();   // staging complete; also retires prior-step smem reads

        // ---- prefetch next step's X (consumed next iteration) ----
        float nx0 = 0.f, nx1 = 0.f, nx2 = 0.f;
        if (leader) {
            const float* xq = (t + 1 < TT) ? xp + H3 : xp;   // clamp at end
            nx0 = __ldcs(xq);
            nx1 = __ldcs(xq + HH);
            nx2 = __ldcs(xq + 2 * HH);
        }

        // ---- matvec: conflict-free LDS.64, 48 FFMA2 ----
        const ull* shu = (const ull*)sh;
        ull a0 = 0ull, a1 = 0ull, a2 = 0ull;
#pragma unroll
        for (int j = 0; j < 16; j++) {
            ull h2 = shu[s + 16 * j];
            FMA2(a0, h2, w2[0][j]);
            FMA2(a1, h2, w2[1][j]);
            FMA2(a2, h2, w2[2][j]);
        }
        float2 f0 = upk2(a0), f1 = upk2(a1), f2 = upk2(a2);
        float s0 = f0.x + f0.y, s1 = f1.x + f1.y, s2 = f2.x + f2.y;
#pragma unroll
        for (int off = 8; off >= 1; off >>= 1) {
            s0 += __shfl_xor_sync(0xffffffffu, s0, off);
            s1 += __shfl_xor_sync(0xffffffffu, s1, off);
            s2 += __shfl_xor_sync(0xffffffffu, s2, off);
        }

        if (leader) {
            float hold = sh[col];
            float zt = 1.f / (1.f + __expf(-(xg0 + s0 + br0)));
            float rt = 1.f / (1.f + __expf(-(xg1 + s1 + br1)));
            float hh = 1.f / (1.f + __expf(-(xg2 + rt * (s2 + br2))));
            float hn = zt * hold + (1.f - zt) * hh;
            // publish h_{t+1}: single relaxed 8B atomic store, tag certifies value
            ull pv = ((ull)__float_as_uint(hn) << 32) | (unsigned)(t + 1);
            st_rlx64(&g_hp[(t + 1) & (RING - 1)][col], pv);
            __stcs(g_seq + (size_t)t * HH + col, hn);
        }
        xg0 = nx0; xg1 = nx1; xg2 = nx2;
        xp += H3;
        // no trailing barrier: next staging writes the OTHER smem buffer, and
        // its barrier proves all reads of this buffer retired before reuse
    }
}

// ---------------- Heads: policy softmax + value + hT ----------------
__global__ __launch_bounds__(256) void k_head(
    const float* __restrict__ Wp, const float* __restrict__ bp,
    const float* __restrict__ Wv, const float* __restrict__ bv,
    float* __restrict__ policy, float* __restrict__ value, float* __restrict__ hT)
{
    __shared__ float sWp[HH * AA];   // 36 KB
    __shared__ float sWv[HH];
    __shared__ float sbp[AA];

    const int tid = threadIdx.x;
    for (int i = tid; i < HH * AA; i += 256) sWp[i] = Wp[i];
    for (int i = tid; i < HH; i += 256) sWv[i] = Wv[i];
    if (tid < AA) sbp[tid] = bp[tid];
    __syncthreads();

    if (blockIdx.x == 0) {
        for (int i = tid; i < HH; i += 256) hT[i] = g_seq[(size_t)(TT - 1) * HH + i];
    }

    const int warp = tid >> 5;
    const int lane = tid & 31;
    const int gwarp = blockIdx.x * 8 + warp;
    const int nwarps = gridDim.x * 8;
    const float bvv = bv[0];

    for (int row = gwarp; row < TT; row += nwarps) {
        float acc[AA + 1];
#pragma unroll
        for (int o = 0; o <= AA; o++) acc[o] = 0.f;

        const float* hrow = g_seq + (size_t)row * HH;
#pragma unroll 4
        for (int i = 0; i < HH / 32; i++) {
            int k = i * 32 + lane;
            float h = hrow[k];
            const float* wr = &sWp[k * AA];
#pragma unroll
            for (int o = 0; o < AA; o++) acc[o] = fmaf(h, wr[o], acc[o]);
            acc[AA] = fmaf(h, sWv[k], acc[AA]);
        }
#pragma unroll
        for (int off = 16; off >= 1; off >>= 1) {
#pragma unroll
            for (int o = 0; o <= AA; o++)
                acc[o] += __shfl_xor_sync(0xffffffffu, acc[o], off);
        }
        if (lane == 0) {
            float logits[AA];
            float mx = -1e30f;
#pragma unroll
            for (int o = 0; o < AA; o++) {
                logits[o] = acc[o] + sbp[o];
                mx = fmaxf(mx, logits[o]);
            }
            float sum = 0.f;
#pragma unroll
            for (int o = 0; o < AA; o++) {
                logits[o] = __expf(logits[o] - mx);
                sum += logits[o];
            }
            float inv = 1.f / sum;
            float* prow = policy + (size_t)row * AA;
#pragma unroll
            for (int o = 0; o < AA; o++) prow[o] = logits[o] * inv;
            value[row] = acc[AA] + bvv;
        }
    }
}

// ---------------- launch ----------------
extern "C" void kernel_launch(void* const* d_in, const int* in_sizes, int n_in,
                              void* d_out, int out_size) {
    const float* x    = (const float*)d_in[0];
    const float* prev = (const float*)d_in[1];
    const float* W1   = (const float*)d_in[2];
    const float* b1   = (const float*)d_in[3];
    const float* W2   = (const float*)d_in[4];
    const float* b2   = (const float*)d_in[5];
    const float* Wg   = (const float*)d_in[6];
    const float* Ug   = (const float*)d_in[7];
    const float* bg   = (const float*)d_in[8];
    const float* Wp   = (const float*)d_in[9];
    const float* bp   = (const float*)d_in[10];
    const float* Wv   = (const float*)d_in[11];
    const float* bv   = (const float*)d_in[12];

    float* out    = (float*)d_out;
    float* policy = out;                        // [T, A]
    float* value  = out + (size_t)TT * AA;      // [T, 1]
    float* hT     = out + (size_t)TT * AA + TT; // [1, H]

    k_init<<<1, 512>>>(prev);

    dim3 blk(256);
    k_gemm1<<<dim3(DD / 64, TT / 128), blk>>>(x, W1, b1);
    k_gemm2<<<dim3(DD / 64, TT / 128), blk>>>(W2, b2);
    k_gemm3<<<dim3(H3 / 64, TT / 128), blk>>>(Wg, bg);

    k_gru<<<NCG, GRU_THREADS>>>(Ug, bg);

    k_head<<<256, 256>>>(Wp, bp, Wv, bv, policy, value, hT);

    (void)in_sizes; (void)n_in; (void)out_size;
}